// round 5
// baseline (speedup 1.0000x reference)
#include <cuda_runtime.h>
#include <cstdint>

typedef unsigned long long u64;

#define KH 3
#define KW 3
#define IN_C 3
#define OUT_C 16
#define QUBITS 5
#define DIM 32
#define FEAT 27
#define EPSV 0.001f
#define IMG 224
#define PADIMG 226
#define BATCH 8
#define CG 4            // channels per thread
#define PX 4            // pixels per thread

// Precomputed circuit rows: g_W2[f*16+k] = (Re U[k,f], Im U[k,f])
__device__ float2 g_W2[FEAT * OUT_C];
// Padded, EPS-added, lane-duplicated input: (v,v) per pixel
__device__ u64 g_xdup[BATCH * IN_C * PADIMG * PADIMG];

// ---------------- packed f32x2 helpers ----------------
__device__ __forceinline__ u64 pack2(float lo, float hi) {
    u64 r; asm("mov.b64 %0, {%1, %2};" : "=l"(r) : "f"(lo), "f"(hi)); return r;
}
__device__ __forceinline__ void unpack2(u64 v, float& lo, float& hi) {
    asm("mov.b64 {%0, %1}, %2;" : "=f"(lo), "=f"(hi) : "l"(v));
}
__device__ __forceinline__ u64 fma2(u64 a, u64 b, u64 c) {
    u64 d; asm("fma.rn.f32x2 %0, %1, %2, %3;" : "=l"(d) : "l"(a), "l"(b), "l"(c)); return d;
}

// ---------------- setup: build U rows from rotation angles ----------------
__global__ void qconv_setup_kernel(const float* __restrict__ w) {
    int f = threadIdx.x;          // 0..31, only f<27 used
    float re[DIM], im[DIM];
#pragma unroll
    for (int i = 0; i < DIM; i++) { re[i] = (i == f) ? 1.0f : 0.0f; im[i] = 0.0f; }

    // Rot(phi,theta,omega) = RZ(omega) RY(theta) RZ(phi) on each qubit
#pragma unroll
    for (int q = 0; q < QUBITS; q++) {
        float phi = w[3 * q + 0], th = w[3 * q + 1], om = w[3 * q + 2];
        float ch = cosf(0.5f * th), sh = sinf(0.5f * th);
        float ap = 0.5f * (phi + om), am = 0.5f * (phi - om);
        float cap = cosf(ap), sap = sinf(ap), cam = cosf(am), sam = sinf(am);
        float u00r =  ch * cap, u00i = -ch * sap;
        float u01r = -sh * cam, u01i = -sh * sam;
        float u10r =  sh * cam, u10i = -sh * sam;
        float u11r =  ch * cap, u11i =  ch * sap;
        const int m = 1 << (4 - q);
#pragma unroll
        for (int i = 0; i < DIM; i++) {
            if (i & m) continue;
            const int j = i | m;
            float r0 = re[i], i0 = im[i], r1 = re[j], i1 = im[j];
            re[i] = u00r * r0 - u00i * i0 + u01r * r1 - u01i * i1;
            im[i] = u00r * i0 + u00i * r0 + u01r * i1 + u01i * r1;
            re[j] = u10r * r0 - u10i * i0 + u11r * r1 - u11i * i1;
            im[j] = u10r * i0 + u10i * r0 + u11r * i1 + u11i * r1;
        }
    }

    // CNOT ring: control q -> target (q+1)%5
#pragma unroll
    for (int q = 0; q < QUBITS; q++) {
        const int mc = 1 << (4 - q);
        const int mt = 1 << (4 - ((q + 1) % QUBITS));
#pragma unroll
        for (int i = 0; i < DIM; i++) {
            if (!(i & mc) || (i & mt)) continue;
            const int j = i | mt;
            float tr = re[i]; re[i] = re[j]; re[j] = tr;
            float ti = im[i]; im[i] = im[j]; im[j] = ti;
        }
    }

    if (f < FEAT) {
#pragma unroll
        for (int k = 0; k < OUT_C; k++) {
            g_W2[f * OUT_C + k] = make_float2(re[k], im[k]);
        }
    }
}

// ---------------- prepass: pad + EPS + duplicate ----------------
__global__ __launch_bounds__(256) void qconv_prepass_kernel(const float* __restrict__ x) {
    const int i = blockIdx.x * 256 + threadIdx.x;
    if (i >= BATCH * IN_C * PADIMG * PADIMG) return;
    const int px = i % PADIMG;
    const int r  = i / PADIMG;
    const int py = r % PADIMG;
    const int bc = r / PADIMG;
    float v = EPSV;
    if (px >= 1 && px <= IMG && py >= 1 && py <= IMG)
        v += __ldg(&x[(size_t)bc * IMG * IMG + (py - 1) * IMG + (px - 1)]);
    g_xdup[i] = pack2(v, v);
}

// ---------------- main: 4 pixels x 4 channels, (Re,Im)-packed accumulators ----------------
__global__ __launch_bounds__(256, 4) void qconv_main_kernel(float* __restrict__ out) {
    __shared__ u64 shW[FEAT * OUT_C];   // (wR, wI) per (f,k)
    for (int i = threadIdx.x; i < FEAT * OUT_C; i += 256)
        reinterpret_cast<float2*>(shW)[i] = g_W2[i];
    __syncthreads();

    const int t   = blockIdx.x * 256 + threadIdx.x;   // pixel-quad index
    const int w0  = (t % (IMG / PX)) * PX;            // multiple of 4
    const int row = t / (IMG / PX);
    const int h   = row % IMG;
    const int b   = row / IMG;
    const int kbase = blockIdx.y * CG;

    u64 acc[PX][CG];
#pragma unroll
    for (int p = 0; p < PX; p++)
#pragma unroll
        for (int k = 0; k < CG; k++) acc[p][k] = 0ull;
    u64 nS[PX + 2];                                   // packed per-column square sums
#pragma unroll
    for (int i = 0; i < PX + 2; i++) nS[i] = 0ull;

    const u64* xb = g_xdup + (size_t)b * IN_C * PADIMG * PADIMG + w0;
    const u64* shWg = shW + kbase;

#pragma unroll 1
    for (int c = 0; c < IN_C; c++) {
#pragma unroll
        for (int di = 0; di < KH; di++) {
            // padded row h+di; columns w0..w0+5 (padded) = original w0-1..w0+4
            const u64* xr = xb + ((size_t)c * PADIMG + (h + di)) * PADIMG;
            ulonglong2 d01 = *reinterpret_cast<const ulonglong2*>(xr);      // 16B-aligned
            ulonglong2 d23 = *reinterpret_cast<const ulonglong2*>(xr + 2);
            ulonglong2 d45 = *reinterpret_cast<const ulonglong2*>(xr + 4);
            u64 dup[PX + 2] = {d01.x, d01.y, d23.x, d23.y, d45.x, d45.y};
#pragma unroll
            for (int i = 0; i < PX + 2; i++)
                nS[i] = fma2(dup[i], dup[i], nS[i]);
#pragma unroll
            for (int dj = 0; dj < KW; dj++) {
                const u64* wr = &shWg[(c * 9 + di * 3 + dj) * OUT_C];
                const ulonglong2 w01 = *reinterpret_cast<const ulonglong2*>(&wr[0]);
                const ulonglong2 w23 = *reinterpret_cast<const ulonglong2*>(&wr[2]);
#pragma unroll
                for (int p = 0; p < PX; p++) {
                    const u64 vv = dup[p + dj];
                    acc[p][0] = fma2(w01.x, vv, acc[p][0]);
                    acc[p][1] = fma2(w01.y, vv, acc[p][1]);
                    acc[p][2] = fma2(w23.x, vv, acc[p][2]);
                    acc[p][3] = fma2(w23.y, vv, acc[p][3]);
                }
            }
        }
    }

    float cs[PX + 2];
#pragma unroll
    for (int i = 0; i < PX + 2; i++) { float lo, hi; unpack2(nS[i], lo, hi); cs[i] = lo; }
    float rn[PX];
#pragma unroll
    for (int p = 0; p < PX; p++)
        rn[p] = __fdividef(8.0f, cs[p] + cs[p + 1] + cs[p + 2]);

    float* ob = out + (size_t)b * OUT_C * IMG * IMG + (size_t)kbase * (IMG * IMG)
              + (size_t)h * IMG + w0;
#pragma unroll
    for (int k = 0; k < CG; k++) {
        float4 o;
        float* ov = reinterpret_cast<float*>(&o);
#pragma unroll
        for (int p = 0; p < PX; p++) {
            float R, I;
            unpack2(acc[p][k], R, I);
            ov[p] = fmaf(R, R, I * I) * rn[p];
        }
        *reinterpret_cast<float4*>(ob + (size_t)k * (IMG * IMG)) = o;   // 16B-aligned
    }
}

extern "C" void kernel_launch(void* const* d_in, const int* in_sizes, int n_in,
                              void* d_out, int out_size) {
    const float* x = (const float*)d_in[0];       // (8,3,224,224) float32
    const float* w = (const float*)d_in[1];       // (1,5,3) float32
    float* out = (float*)d_out;                   // (8,16,224,224) float32
    (void)in_sizes; (void)n_in; (void)out_size;

    qconv_setup_kernel<<<1, 32>>>(w);
    const int nprep = BATCH * IN_C * PADIMG * PADIMG;
    qconv_prepass_kernel<<<(nprep + 255) / 256, 256>>>(x);
    const int nquads = BATCH * IMG * (IMG / PX);  // 100352
    dim3 grid(nquads / 256, OUT_C / CG);          // (392, 4)
    qconv_main_kernel<<<grid, 256>>>(out);
}

// round 6
// speedup vs baseline: 1.8430x; 1.8430x over previous
#include <cuda_runtime.h>
#include <cstdint>

typedef unsigned long long u64;

#define KH 3
#define KW 3
#define IN_C 3
#define OUT_C 16
#define QUBITS 5
#define DIM 32
#define FEAT 27
#define EPSV 0.001f
#define IMG 224
#define BATCH 8
#define CG 4            // channels per thread
#define PX 4            // pixels per thread

// Staging (written by setup kernel), then copied into constant memory.
__device__ float2 g_W2[FEAT * OUT_C];
// Weight table in constant memory: (Re U[k,f], Im U[k,f]) packed as u64 per (f,k).
// Accesses are warp-uniform -> served by the constant port, not L1/shared.
__constant__ u64 c_W[FEAT * OUT_C];

// ---------------- packed f32x2 helpers ----------------
__device__ __forceinline__ u64 pack2(float lo, float hi) {
    u64 r; asm("mov.b64 %0, {%1, %2};" : "=l"(r) : "f"(lo), "f"(hi)); return r;
}
__device__ __forceinline__ void unpack2(u64 v, float& lo, float& hi) {
    asm("mov.b64 {%0, %1}, %2;" : "=f"(lo), "=f"(hi) : "l"(v));
}
__device__ __forceinline__ u64 fma2(u64 a, u64 b, u64 c) {
    u64 d; asm("fma.rn.f32x2 %0, %1, %2, %3;" : "=l"(d) : "l"(a), "l"(b), "l"(c)); return d;
}

// ---------------- setup: build U rows from rotation angles ----------------
__global__ void qconv_setup_kernel(const float* __restrict__ w) {
    int f = threadIdx.x;          // 0..31, only f<27 used
    float re[DIM], im[DIM];
#pragma unroll
    for (int i = 0; i < DIM; i++) { re[i] = (i == f) ? 1.0f : 0.0f; im[i] = 0.0f; }

    // Rot(phi,theta,omega) = RZ(omega) RY(theta) RZ(phi) on each qubit
#pragma unroll
    for (int q = 0; q < QUBITS; q++) {
        float phi = w[3 * q + 0], th = w[3 * q + 1], om = w[3 * q + 2];
        float ch = cosf(0.5f * th), sh = sinf(0.5f * th);
        float ap = 0.5f * (phi + om), am = 0.5f * (phi - om);
        float cap = cosf(ap), sap = sinf(ap), cam = cosf(am), sam = sinf(am);
        float u00r =  ch * cap, u00i = -ch * sap;
        float u01r = -sh * cam, u01i = -sh * sam;
        float u10r =  sh * cam, u10i = -sh * sam;
        float u11r =  ch * cap, u11i =  ch * sap;
        const int m = 1 << (4 - q);
#pragma unroll
        for (int i = 0; i < DIM; i++) {
            if (i & m) continue;
            const int j = i | m;
            float r0 = re[i], i0 = im[i], r1 = re[j], i1 = im[j];
            re[i] = u00r * r0 - u00i * i0 + u01r * r1 - u01i * i1;
            im[i] = u00r * i0 + u00i * r0 + u01r * i1 + u01i * r1;
            re[j] = u10r * r0 - u10i * i0 + u11r * r1 - u11i * i1;
            im[j] = u10r * i0 + u10i * r0 + u11r * i1 + u11i * r1;
        }
    }

    // CNOT ring: control q -> target (q+1)%5
#pragma unroll
    for (int q = 0; q < QUBITS; q++) {
        const int mc = 1 << (4 - q);
        const int mt = 1 << (4 - ((q + 1) % QUBITS));
#pragma unroll
        for (int i = 0; i < DIM; i++) {
            if (!(i & mc) || (i & mt)) continue;
            const int j = i | mt;
            float tr = re[i]; re[i] = re[j]; re[j] = tr;
            float ti = im[i]; im[i] = im[j]; im[j] = ti;
        }
    }

    if (f < FEAT) {
#pragma unroll
        for (int k = 0; k < OUT_C; k++) {
            g_W2[f * OUT_C + k] = make_float2(re[k], im[k]);
        }
    }
}

// ---------------- main: 4 pixels x 4 channels, weights from constant memory ----------------
__global__ __launch_bounds__(256, 4) void qconv_main_kernel(const float* __restrict__ x,
                                                            float* __restrict__ out) {
    const int t   = blockIdx.x * 256 + threadIdx.x;   // pixel-quad index
    const int w0  = (t % (IMG / PX)) * PX;            // multiple of 4
    const int row = t / (IMG / PX);
    const int h   = row % IMG;
    const int b   = row / IMG;
    const int kbase = blockIdx.y * CG;

    u64 acc[PX][CG];
#pragma unroll
    for (int p = 0; p < PX; p++)
#pragma unroll
        for (int k = 0; k < CG; k++) acc[p][k] = 0ull;
    float S[PX + 2];                                  // per-column square sums
#pragma unroll
    for (int i = 0; i < PX + 2; i++) S[i] = 0.0f;

    const float* xb = x + (size_t)b * IN_C * IMG * IMG;
    const u64* cWg = c_W + kbase;
    const bool le  = (w0 > 0);
    const bool re_ = (w0 < IMG - PX);

#pragma unroll 1
    for (int c = 0; c < IN_C; c++) {
#pragma unroll
        for (int di = 0; di < KH; di++) {
            const int y = h + di - 1;
            const bool ok = ((unsigned)y < (unsigned)IMG);
            const float* rp = xb + ((size_t)c * IMG + y) * IMG + w0;
            float te[PX + 2];
            if (ok) {
                const float4 q = *reinterpret_cast<const float4*>(rp);
                te[0] = le  ? __ldg(rp - 1) : 0.0f;
                te[1] = q.x; te[2] = q.y; te[3] = q.z; te[4] = q.w;
                te[5] = re_ ? __ldg(rp + PX) : 0.0f;
            } else {
#pragma unroll
                for (int i = 0; i < PX + 2; i++) te[i] = 0.0f;
            }
            u64 dup[PX + 2];
#pragma unroll
            for (int i = 0; i < PX + 2; i++) {
                te[i] += EPSV;
                S[i] = fmaf(te[i], te[i], S[i]);
                dup[i] = pack2(te[i], te[i]);
            }
#pragma unroll
            for (int dj = 0; dj < KW; dj++) {
                const u64* wr = &cWg[(c * 9 + di * 3 + dj) * OUT_C];
                const u64 wk0 = wr[0];
                const u64 wk1 = wr[1];
                const u64 wk2 = wr[2];
                const u64 wk3 = wr[3];
#pragma unroll
                for (int p = 0; p < PX; p++) {
                    const u64 vv = dup[p + dj];
                    acc[p][0] = fma2(wk0, vv, acc[p][0]);
                    acc[p][1] = fma2(wk1, vv, acc[p][1]);
                    acc[p][2] = fma2(wk2, vv, acc[p][2]);
                    acc[p][3] = fma2(wk3, vv, acc[p][3]);
                }
            }
        }
    }

    float rn[PX];
#pragma unroll
    for (int p = 0; p < PX; p++)
        rn[p] = __fdividef(8.0f, S[p] + S[p + 1] + S[p + 2]);

    float* ob = out + (size_t)b * OUT_C * IMG * IMG + (size_t)kbase * (IMG * IMG)
              + (size_t)h * IMG + w0;
#pragma unroll
    for (int k = 0; k < CG; k++) {
        float4 o;
        float* ov = reinterpret_cast<float*>(&o);
#pragma unroll
        for (int p = 0; p < PX; p++) {
            float R, I;
            unpack2(acc[p][k], R, I);
            ov[p] = fmaf(R, R, I * I) * rn[p];
        }
        *reinterpret_cast<float4*>(ob + (size_t)k * (IMG * IMG)) = o;   // 16B-aligned
    }
}

extern "C" void kernel_launch(void* const* d_in, const int* in_sizes, int n_in,
                              void* d_out, int out_size) {
    const float* x = (const float*)d_in[0];       // (8,3,224,224) float32
    const float* w = (const float*)d_in[1];       // (1,5,3) float32
    float* out = (float*)d_out;                   // (8,16,224,224) float32
    (void)in_sizes; (void)n_in; (void)out_size;

    qconv_setup_kernel<<<1, 32>>>(w);

    // Copy computed weights into constant memory (device-to-device, capturable).
    void* src = nullptr;
    cudaGetSymbolAddress(&src, g_W2);
    cudaMemcpyToSymbolAsync(c_W, src, sizeof(u64) * FEAT * OUT_C, 0,
                            cudaMemcpyDeviceToDevice);

    const int nquads = BATCH * IMG * (IMG / PX);  // 100352
    dim3 grid(nquads / 256, OUT_C / CG);          // (392, 4)
    qconv_main_kernel<<<grid, 256>>>(x, out);
}

// round 7
// speedup vs baseline: 1.8781x; 1.0190x over previous
#include <cuda_runtime.h>
#include <cstdint>

typedef unsigned long long u64;

#define KH 3
#define KW 3
#define IN_C 3
#define OUT_C 16
#define QUBITS 5
#define DIM 32
#define FEAT 27
#define EPSV 0.001f
#define IMG 224
#define BATCH 8
#define CG 4            // channels per thread
#define PX 4            // pixels per thread

// Staging (written by setup kernel), then copied into constant memory.
__device__ float2 g_W2[FEAT * OUT_C];
// Weight table in constant memory: (Re U[k,f], Im U[k,f]) packed as u64 per (f,k).
__constant__ u64 c_W[FEAT * OUT_C];

// ---------------- packed f32x2 helpers ----------------
__device__ __forceinline__ u64 pack2(float lo, float hi) {
    u64 r; asm("mov.b64 %0, {%1, %2};" : "=l"(r) : "f"(lo), "f"(hi)); return r;
}
__device__ __forceinline__ void unpack2(u64 v, float& lo, float& hi) {
    asm("mov.b64 {%0, %1}, %2;" : "=f"(lo), "=f"(hi) : "l"(v));
}
__device__ __forceinline__ u64 fma2(u64 a, u64 b, u64 c) {
    u64 d; asm("fma.rn.f32x2 %0, %1, %2, %3;" : "=l"(d) : "l"(a), "l"(b), "l"(c)); return d;
}

// ---------------- setup: warp-per-column circuit simulation ----------------
// Warp f (threadIdx.y) simulates the circuit on basis state e_f.
// Lane l holds the complex amplitude of basis state l. Qubit q <-> bit (4-q).
__global__ void qconv_setup_kernel(const float* __restrict__ w) {
    const int f    = threadIdx.y;      // 0..26 column
    const int lane = threadIdx.x;      // 0..31 basis state
    float ar = (lane == f) ? 1.0f : 0.0f;
    float ai = 0.0f;

    // Rot(phi,theta,omega) = RZ(omega) RY(theta) RZ(phi) on each qubit
#pragma unroll
    for (int q = 0; q < QUBITS; q++) {
        const float phi = __ldg(&w[3 * q + 0]);
        const float th  = __ldg(&w[3 * q + 1]);
        const float om  = __ldg(&w[3 * q + 2]);
        const float ch = cosf(0.5f * th), sh = sinf(0.5f * th);
        const float ap = 0.5f * (phi + om), am = 0.5f * (phi - om);
        const float cap = cosf(ap), sap = sinf(ap);
        const float cam = cosf(am), sam = sinf(am);
        const float u00r =  ch * cap, u00i = -ch * sap;
        const float u01r = -sh * cam, u01i = -sh * sam;
        const float u10r =  sh * cam, u10i = -sh * sam;
        const float u11r =  ch * cap, u11i =  ch * sap;
        const int m = 1 << (4 - q);
        const float pr = __shfl_xor_sync(0xFFFFFFFFu, ar, m);
        const float pi = __shfl_xor_sync(0xFFFFFFFFu, ai, m);
        float nr, ni;
        if (lane & m) {   // this lane is the |1> component: partner is |0>
            nr = u10r * pr - u10i * pi + u11r * ar - u11i * ai;
            ni = u10r * pi + u10i * pr + u11r * ai + u11i * ar;
        } else {          // |0> component: partner is |1>
            nr = u00r * ar - u00i * ai + u01r * pr - u01i * pi;
            ni = u00r * ai + u00i * ar + u01r * pi + u01i * pr;
        }
        ar = nr; ai = ni;
    }

    // CNOT ring: control q -> target (q+1)%5
#pragma unroll
    for (int q = 0; q < QUBITS; q++) {
        const int mc = 1 << (4 - q);
        const int mt = 1 << (4 - ((q + 1) % QUBITS));
        const float pr = __shfl_xor_sync(0xFFFFFFFFu, ar, mt);
        const float pi = __shfl_xor_sync(0xFFFFFFFFu, ai, mt);
        if (lane & mc) { ar = pr; ai = pi; }
    }

    if (lane < OUT_C)
        g_W2[f * OUT_C + lane] = make_float2(ar, ai);
}

// ---------------- main: 4 pixels x 4 channels, weights via LDC.128 ----------------
__global__ __launch_bounds__(256, 4) void qconv_main_kernel(const float* __restrict__ x,
                                                            float* __restrict__ out) {
    const int t   = blockIdx.x * 256 + threadIdx.x;   // pixel-quad index
    const int w0  = (t % (IMG / PX)) * PX;            // multiple of 4
    const int row = t / (IMG / PX);
    const int h   = row % IMG;
    const int b   = row / IMG;
    const int kbase = blockIdx.y * CG;

    u64 acc[PX][CG];
#pragma unroll
    for (int p = 0; p < PX; p++)
#pragma unroll
        for (int k = 0; k < CG; k++) acc[p][k] = 0ull;
    float S[PX + 2];                                  // per-column square sums
#pragma unroll
    for (int i = 0; i < PX + 2; i++) S[i] = 0.0f;

    const float* xb = x + (size_t)b * IN_C * IMG * IMG;
    const u64* cWg = c_W + kbase;
    const bool le  = (w0 > 0);
    const bool re_ = (w0 < IMG - PX);

#pragma unroll 1
    for (int c = 0; c < IN_C; c++) {
#pragma unroll
        for (int di = 0; di < KH; di++) {
            const int y = h + di - 1;
            const bool ok = ((unsigned)y < (unsigned)IMG);
            const float* rp = xb + ((size_t)c * IMG + y) * IMG + w0;
            float te[PX + 2];
            if (ok) {
                const float4 q = *reinterpret_cast<const float4*>(rp);
                te[0] = le  ? __ldg(rp - 1) : 0.0f;
                te[1] = q.x; te[2] = q.y; te[3] = q.z; te[4] = q.w;
                te[5] = re_ ? __ldg(rp + PX) : 0.0f;
            } else {
#pragma unroll
                for (int i = 0; i < PX + 2; i++) te[i] = 0.0f;
            }
            u64 dup[PX + 2];
#pragma unroll
            for (int i = 0; i < PX + 2; i++) {
                te[i] += EPSV;
                S[i] = fmaf(te[i], te[i], S[i]);
                dup[i] = pack2(te[i], te[i]);
            }
#pragma unroll
            for (int dj = 0; dj < KW; dj++) {
                const u64* wr = &cWg[(c * 9 + di * 3 + dj) * OUT_C];
                const ulonglong2 w01 = *reinterpret_cast<const ulonglong2*>(&wr[0]); // LDC.128
                const ulonglong2 w23 = *reinterpret_cast<const ulonglong2*>(&wr[2]); // LDC.128
#pragma unroll
                for (int p = 0; p < PX; p++) {
                    const u64 vv = dup[p + dj];
                    acc[p][0] = fma2(w01.x, vv, acc[p][0]);
                    acc[p][1] = fma2(w01.y, vv, acc[p][1]);
                    acc[p][2] = fma2(w23.x, vv, acc[p][2]);
                    acc[p][3] = fma2(w23.y, vv, acc[p][3]);
                }
            }
        }
    }

    float rn[PX];
#pragma unroll
    for (int p = 0; p < PX; p++)
        rn[p] = __fdividef(8.0f, S[p] + S[p + 1] + S[p + 2]);

    float* ob = out + (size_t)b * OUT_C * IMG * IMG + (size_t)kbase * (IMG * IMG)
              + (size_t)h * IMG + w0;
#pragma unroll
    for (int k = 0; k < CG; k++) {
        float4 o;
        float* ov = reinterpret_cast<float*>(&o);
#pragma unroll
        for (int p = 0; p < PX; p++) {
            float R, I;
            unpack2(acc[p][k], R, I);
            ov[p] = fmaf(R, R, I * I) * rn[p];
        }
        *reinterpret_cast<float4*>(ob + (size_t)k * (IMG * IMG)) = o;   // 16B-aligned
    }
}

extern "C" void kernel_launch(void* const* d_in, const int* in_sizes, int n_in,
                              void* d_out, int out_size) {
    const float* x = (const float*)d_in[0];       // (8,3,224,224) float32
    const float* w = (const float*)d_in[1];       // (1,5,3) float32
    float* out = (float*)d_out;                   // (8,16,224,224) float32
    (void)in_sizes; (void)n_in; (void)out_size;

    qconv_setup_kernel<<<1, dim3(32, FEAT)>>>(w);

    // Copy computed weights into constant memory (device-to-device, capturable).
    void* src = nullptr;
    cudaGetSymbolAddress(&src, g_W2);
    cudaMemcpyToSymbolAsync(c_W, src, sizeof(u64) * FEAT * OUT_C, 0,
                            cudaMemcpyDeviceToDevice);

    const int nquads = BATCH * IMG * (IMG / PX);  // 100352
    dim3 grid(nquads / 256, OUT_C / CG);          // (392, 4)
    qconv_main_kernel<<<grid, 256>>>(x, out);
}